// round 12
// baseline (speedup 1.0000x reference)
#include <cuda_runtime.h>
#include <cuda_fp16.h>

// Problem constants
#define Bsz    2
#define Nseq   2048
#define Dmodel 1024
#define Hh     16
#define DKh    64
#define Mrows  4096
#define NELEM  (Mrows * Dmodel)     // 4,194,304
#define WELEM  (Dmodel * Dmodel)    // 1,048,576
#define SCALE  0.125f
#define QSCALE (0.125f * 1.44269504088896f)   // fold log2(e): softmax in exp2 domain

// ---- mma.sync / ldmatrix / cp.async helpers (base sm_80+ ISA) ----
__device__ __forceinline__ unsigned smem_u32(const void* p) {
    unsigned a;
    asm("{ .reg .u64 t; cvta.to.shared.u64 t, %1; cvt.u32.u64 %0, t; }" : "=r"(a) : "l"(p));
    return a;
}
__device__ __forceinline__ void ldsm_x4(unsigned& r0, unsigned& r1, unsigned& r2, unsigned& r3,
                                        unsigned addr) {
    asm volatile("ldmatrix.sync.aligned.m8n8.x4.shared.b16 {%0,%1,%2,%3}, [%4];"
                 : "=r"(r0), "=r"(r1), "=r"(r2), "=r"(r3) : "r"(addr));
}
__device__ __forceinline__ void ldsm_x4_t(unsigned& r0, unsigned& r1, unsigned& r2, unsigned& r3,
                                          unsigned addr) {
    asm volatile("ldmatrix.sync.aligned.m8n8.x4.trans.shared.b16 {%0,%1,%2,%3}, [%4];"
                 : "=r"(r0), "=r"(r1), "=r"(r2), "=r"(r3) : "r"(addr));
}
__device__ __forceinline__ void mma16816h(float* c, const unsigned* a, const unsigned* b) {
    asm volatile("mma.sync.aligned.m16n8k16.row.col.f32.f16.f16.f32 "
                 "{%0,%1,%2,%3},{%4,%5,%6,%7},{%8,%9},{%0,%1,%2,%3};"
                 : "+f"(c[0]), "+f"(c[1]), "+f"(c[2]), "+f"(c[3])
                 : "r"(a[0]), "r"(a[1]), "r"(a[2]), "r"(a[3]), "r"(b[0]), "r"(b[1]));
}
__device__ __forceinline__ void cpa16(unsigned dst, const void* src) {
    asm volatile("cp.async.cg.shared.global [%0], [%1], 16;" :: "r"(dst), "l"(src));
}
__device__ __forceinline__ void cpa_commit() { asm volatile("cp.async.commit_group;"); }
template<int N> __device__ __forceinline__ void cpa_wait() {
    asm volatile("cp.async.wait_group %0;" :: "n"(N));
}
__device__ __forceinline__ unsigned packf16(float x, float y) {
    __half2 t = __floats2half2_rn(x, y);
    return *reinterpret_cast<unsigned*>(&t);
}
__device__ __forceinline__ unsigned ex2h2(unsigned d) {
    unsigned e;
    asm("ex2.approx.f16x2 %0, %1;" : "=r"(e) : "r"(d));
    return e;
}

// ---- scratch (fp16) ----
__device__ __half g_xf[3 * NELEM];   // converted inputs q,k,v
__device__ __half g_wf[4 * WELEM];   // converted weights Wq,Wk,Wv,Wo
__device__ __half g_pf[3 * NELEM];   // projected Q(pre-scaled),K,V
__device__ __half g_Cf[NELEM];       // attention output

// ---------------------------------------------------------------------------
// Single convert kernel: z=0..2 inputs (NELEM), z=3..6 weights (WELEM)
// ---------------------------------------------------------------------------
__global__ __launch_bounds__(256) void conv_all(const float* __restrict__ q,
                                                const float* __restrict__ k,
                                                const float* __restrict__ v,
                                                const float* __restrict__ wq,
                                                const float* __restrict__ wk,
                                                const float* __restrict__ wv,
                                                const float* __restrict__ wo)
{
    const int z = blockIdx.z;
    const float* srcs[7] = {q, k, v, wq, wk, wv, wo};
    const float* src = srcs[z];
    __half* dst = (z < 3) ? (g_xf + (size_t)z * NELEM)
                          : (g_wf + (size_t)(z - 3) * WELEM);
    const size_t lim = (z < 3) ? NELEM : WELEM;
    const size_t i = ((size_t)blockIdx.x * 256 + threadIdx.x) * 4;
    if (i >= lim) return;
    float4 f = *(const float4*)(src + i);
    uint2 o;
    o.x = packf16(f.x, f.y);
    o.y = packf16(f.z, f.w);
    *(uint2*)(dst + i) = o;
}

// ---------------------------------------------------------------------------
// fp16 HMMA GEMM, cp.async 3-stage ring, ONE barrier per chunk.
// Tile 128x128, Kc=64, 8 warps (2x4), warp tile 64x32.
// ---------------------------------------------------------------------------
#define KC 64
#define NCH (Dmodel / KC)     // 16
#define GST 72
#define GBUF (128 * GST * 2)  // 18432 B
#define GSTAGE (2 * GBUF)     // 36864 B
#define GSMEM (3 * GSTAGE)    // 110592 B

__device__ __forceinline__ void g_load(unsigned sbase, int stage,
                                       const __half* Xf, const __half* Wf,
                                       int m0, int n0, int k0, int tid)
{
    const int row = tid >> 1;
    const int co  = (tid & 1) * 32;
    const unsigned dst0 = sbase + (unsigned)(stage * GSTAGE + row * 144 + (tid & 1) * 64);
    const size_t asrc = (size_t)(m0 + row) * Dmodel + k0 + co;
    const size_t bsrc = (size_t)(n0 + row) * Dmodel + k0 + co;
#pragma unroll
    for (int j = 0; j < 4; j++) {
        cpa16(dst0 + j * 16,        Xf + asrc + j * 8);
        cpa16(dst0 + GBUF + j * 16, Wf + bsrc + j * 8);
    }
}

__device__ __forceinline__ void gemm_body(const __half* __restrict__ Xf,
                                          const __half* __restrict__ Wf,
                                          const float* __restrict__ bias,
                                          __half* C16, float* Cf, float cscale)
{
    extern __shared__ __align__(16) char smg[];
    const unsigned sbase = smem_u32(smg);

    const int tid  = threadIdx.x;
    const int wid  = tid >> 5;
    const int lane = tid & 31;
    const int wm   = wid >> 2;
    const int wn   = wid & 3;
    const int m0   = blockIdx.y * 128;
    const int n0   = blockIdx.x * 128;

    float acc[4][4][4];
#pragma unroll
    for (int mt = 0; mt < 4; mt++)
#pragma unroll
        for (int nt = 0; nt < 4; nt++)
#pragma unroll
            for (int i = 0; i < 4; i++) acc[mt][nt][i] = 0.0f;

    const unsigned a_off = (unsigned)(((wm * 64 + (lane & 15)) * GST + (lane >> 4) * 8) * 2);
    const unsigned b_off = (unsigned)(((wn * 32 + (lane & 15)) * GST + (lane >> 4) * 8) * 2);

    g_load(sbase, 0, Xf, Wf, m0, n0, 0, tid);
    cpa_commit();
    g_load(sbase, 1, Xf, Wf, m0, n0, KC, tid);
    cpa_commit();

    int stage = 0;
    for (int ch = 0; ch < NCH; ch++) {
        if (ch >= NCH - 1) cpa_wait<0>(); else cpa_wait<1>();
        __syncthreads();   // stage (ch%3) ready for ALL warps; buffer (ch+2)%3 free

        // prefetch chunk ch+2 into the ring slot freed by iteration ch-1
        if (ch + 2 < NCH) {
            int s2 = stage + 2; if (s2 >= 3) s2 -= 3;
            g_load(sbase, s2, Xf, Wf, m0, n0, (ch + 2) * KC, tid);
            cpa_commit();
        }

        const unsigned st = sbase + (unsigned)(stage * GSTAGE);
        const unsigned abase = st + a_off;
        const unsigned bbase = st + GBUF + b_off;

#pragma unroll
        for (int ks = 0; ks < 4; ks++) {
            const unsigned koff = (unsigned)(ks * 16 * 2);
            unsigned bf[4][2];
#pragma unroll
            for (int np = 0; np < 2; np++) {
                unsigned r0, r1, r2, r3;
                ldsm_x4(r0, r1, r2, r3,
                        bbase + koff + (unsigned)(np * 16 * GST * 2));
                bf[np * 2 + 0][0] = r0; bf[np * 2 + 0][1] = r2;
                bf[np * 2 + 1][0] = r1; bf[np * 2 + 1][1] = r3;
            }
            unsigned af[4][4];
#pragma unroll
            for (int mt = 0; mt < 4; mt++)
                ldsm_x4(af[mt][0], af[mt][1], af[mt][2], af[mt][3],
                        abase + koff + (unsigned)(mt * 16 * GST * 2));
#pragma unroll
            for (int mt = 0; mt < 4; mt++)
#pragma unroll
                for (int nt = 0; nt < 4; nt++)
                    mma16816h(acc[mt][nt], af[mt], bf[nt]);
        }

        if (++stage >= 3) stage = 0;
    }

    const int g   = lane >> 2;
    const int tig = lane & 3;
#pragma unroll
    for (int mt = 0; mt < 4; mt++) {
        const int r0 = m0 + wm * 64 + mt * 16 + g;
#pragma unroll
        for (int nt = 0; nt < 4; nt++) {
            const int cidx = n0 + wn * 32 + nt * 8 + tig * 2;
            const float2 bv = *(const float2*)(bias + cidx);
            const float x0 = acc[mt][nt][0] + bv.x;
            const float x1 = acc[mt][nt][1] + bv.y;
            const float x2 = acc[mt][nt][2] + bv.x;
            const float x3 = acc[mt][nt][3] + bv.y;
            if (Cf) {
                *(float2*)(Cf + (size_t)r0 * Dmodel + cidx) = make_float2(x0, x1);
                *(float2*)(Cf + (size_t)(r0 + 8) * Dmodel + cidx) = make_float2(x2, x3);
            } else {
                *(unsigned*)(C16 + (size_t)r0 * Dmodel + cidx) =
                    packf16(x0 * cscale, x1 * cscale);
                *(unsigned*)(C16 + (size_t)(r0 + 8) * Dmodel + cidx) =
                    packf16(x2 * cscale, x3 * cscale);
            }
        }
    }
}

__global__ __launch_bounds__(256, 2) void qkv_gemm(const float* __restrict__ bq,
                                                   const float* __restrict__ bk,
                                                   const float* __restrict__ bv)
{
    const int z = blockIdx.z;
    const float* bias = (z == 0) ? bq : (z == 1) ? bk : bv;
    const float cs = (z == 0) ? QSCALE : 1.0f;
    gemm_body(g_xf + (size_t)z * NELEM, g_wf + (size_t)z * WELEM,
              bias, g_pf + (size_t)z * NELEM, nullptr, cs);
}

__global__ __launch_bounds__(256, 2) void out_gemm(const float* __restrict__ bo,
                                                   float* __restrict__ out)
{
    gemm_body(g_Cf, g_wf + (size_t)3 * WELEM, bo, nullptr, out, 1.0f);
}

// ---------------------------------------------------------------------------
// Flash attention, fp16 HMMA, cp.async 3-stage K/V ring, ONE barrier per tile.
// half2 softmax via ex2.approx.f16x2 (output IS the PV fragment).
// CTA: 128 q-rows x (b,h); 8 warps x 16 rows; j-tiles of 64.
// ---------------------------------------------------------------------------
#define FST 72
#define QBUF  (128 * FST * 2)     // 18432
#define KVBUF (64 * FST * 2)      // 9216
#define KVSTAGE (2 * KVBUF)       // 18432
#define FSMEM (QBUF + 3 * KVSTAGE)   // 73728

__device__ __forceinline__ void f_loadKV(unsigned kvbase, int stage, int jt,
                                         const __half* Kf, const __half* Vf, int tid)
{
    const int row = tid >> 2;
    const int c2  = tid & 3;
    const unsigned dst0 = kvbase + (unsigned)(stage * KVSTAGE + row * 144 + c2 * 32);
    const size_t src = (size_t)(jt + row) * Dmodel + c2 * 16;
    cpa16(dst0,              Kf + src);
    cpa16(dst0 + 16,         Kf + src + 8);
    cpa16(dst0 + KVBUF,      Vf + src);
    cpa16(dst0 + KVBUF + 16, Vf + src + 8);
}

__global__ __launch_bounds__(256, 2) void flash_attn()
{
    extern __shared__ __align__(16) char smf[];
    const unsigned sbase  = smem_u32(smf);
    const unsigned kvbase = sbase + QBUF;

    const int tid  = threadIdx.x;
    const int wid  = tid >> 5;
    const int lane = tid & 31;
    const int tg   = lane & 3;
    const int bh   = blockIdx.y;
    const int b    = bh >> 4;
    const int h    = bh & 15;
    const int q0   = blockIdx.x * 128;

    const size_t hoff = (size_t)b * Nseq * Dmodel + h * DKh;
    const __half* Qf = g_pf + hoff;
    const __half* Kf = g_pf + NELEM + hoff;
    const __half* Vf = g_pf + 2 * NELEM + hoff;

    // prologue: Q + KV tiles 0,1
    {
        const int row = tid >> 1;
        const int c4  = tid & 1;
        const unsigned dq = sbase + (unsigned)(row * 144 + c4 * 64);
        const size_t src = (size_t)(q0 + row) * Dmodel + c4 * 32;
#pragma unroll
        for (int j = 0; j < 4; j++)
            cpa16(dq + j * 16, Qf + src + j * 8);
    }
    f_loadKV(kvbase, 0, 0, Kf, Vf, tid);
    cpa_commit();
    f_loadKV(kvbase, 1, 64, Kf, Vf, tid);
    cpa_commit();
    cpa_wait<1>();
    __syncthreads();   // Q + KV tile 0 ready

    // persistent Q fragments
    const unsigned qa = sbase +
        (unsigned)(((wid * 16 + (lane & 15)) * FST + (lane >> 4) * 8) * 2);
    unsigned aq[4][4];
#pragma unroll
    for (int ks = 0; ks < 4; ks++)
        ldsm_x4(aq[ks][0], aq[ks][1], aq[ks][2], aq[ks][3], qa + ks * 32);

    const unsigned kb_off = (unsigned)(((lane & 15) * FST + (lane >> 4) * 8) * 2);

    float oacc[8][4];
#pragma unroll
    for (int nt = 0; nt < 8; nt++)
#pragma unroll
        for (int i = 0; i < 4; i++) oacc[nt][i] = 0.0f;
    float mr0 = -1e30f, mr1 = -1e30f, lr0 = 0.0f, lr1 = 0.0f;

    const int NT = Nseq / 64;   // 32
    int stage = 0;
    for (int jt = 0; jt < NT; jt++) {
        if (jt > 0) {            // tile 0 already waited in prologue
            if (jt >= NT - 1) cpa_wait<0>(); else cpa_wait<1>();
            __syncthreads();     // stage ready; ring slot (jt+2)%3 free
        }
        // prefetch tile jt+2 into freed ring slot
        if (jt + 2 < NT) {
            int s2 = stage + 2; if (s2 >= 3) s2 -= 3;
            f_loadKV(kvbase, s2, (jt + 2) * 64, Kf, Vf, tid);
            cpa_commit();
        }

        const unsigned st = kvbase + (unsigned)(stage * KVSTAGE);
        const unsigned kb = st + kb_off;
        const unsigned vb = st + KVBUF + kb_off;

        // ---- S = Q K^T (log2 domain; scale pre-folded into Q) ----
        float sacc[8][4];
#pragma unroll
        for (int nt = 0; nt < 8; nt++)
#pragma unroll
            for (int i = 0; i < 4; i++) sacc[nt][i] = 0.0f;

        {
            unsigned kf[2][4];
            ldsm_x4(kf[0][0], kf[0][1], kf[0][2], kf[0][3], kb);
#pragma unroll
            for (int it = 0; it < 16; it++) {
                const int ks = it >> 2, jb = it & 3;
                if (it + 1 < 16) {
                    const int ks2 = (it + 1) >> 2, jb2 = (it + 1) & 3;
                    ldsm_x4(kf[(it + 1) & 1][0], kf[(it + 1) & 1][1],
                            kf[(it + 1) & 1][2], kf[(it + 1) & 1][3],
                            kb + (unsigned)((jb2 * 16 * FST + ks2 * 16) * 2));
                }
                unsigned bf0[2] = {kf[it & 1][0], kf[it & 1][2]};
                unsigned bf1[2] = {kf[it & 1][1], kf[it & 1][3]};
                mma16816h(sacc[jb * 2 + 0], aq[ks], bf0);
                mma16816h(sacc[jb * 2 + 1], aq[ks], bf1);
            }
        }

        // ---- online softmax (half2 exp) ----
        float mx0 = -1e30f, mx1 = -1e30f;
#pragma unroll
        for (int nt = 0; nt < 8; nt++) {
            mx0 = fmaxf(mx0, fmaxf(sacc[nt][0], sacc[nt][1]));
            mx1 = fmaxf(mx1, fmaxf(sacc[nt][2], sacc[nt][3]));
        }
        mx0 = fmaxf(mx0, __shfl_xor_sync(0xffffffffu, mx0, 1));
        mx0 = fmaxf(mx0, __shfl_xor_sync(0xffffffffu, mx0, 2));
        mx1 = fmaxf(mx1, __shfl_xor_sync(0xffffffffu, mx1, 1));
        mx1 = fmaxf(mx1, __shfl_xor_sync(0xffffffffu, mx1, 2));
        const float mn0 = fmaxf(mr0, mx0);
        const float mn1 = fmaxf(mr1, mx1);
        const float al0 = exp2f(mr0 - mn0);
        const float al1 = exp2f(mr1 - mn1);

        unsigned pa[4][4];
        float rs0 = 0.0f, rs1 = 0.0f;
#pragma unroll
        for (int grp = 0; grp < 2; grp++) {
            __half2 a01 = __float2half2_rn(0.0f);
            __half2 a23 = __float2half2_rn(0.0f);
#pragma unroll
            for (int k2 = 0; k2 < 4; k2++) {
                const int nt = grp * 4 + k2;
                const unsigned e01 = ex2h2(packf16(sacc[nt][0] - mn0, sacc[nt][1] - mn0));
                const unsigned e23 = ex2h2(packf16(sacc[nt][2] - mn1, sacc[nt][3] - mn1));
                const int t = nt >> 1;
                if ((nt & 1) == 0) { pa[t][0] = e01; pa[t][1] = e23; }
                else               { pa[t][2] = e01; pa[t][3] = e23; }
                a01 = __hadd2(a01, *reinterpret_cast<const __half2*>(&e01));
                a23 = __hadd2(a23, *reinterpret_cast<const __half2*>(&e23));
            }
            const float2 f01 = __half22float2(a01);
            const float2 f23 = __half22float2(a23);
            rs0 += f01.x + f01.y;
            rs1 += f23.x + f23.y;
        }
        const bool nochg = (al0 == 1.0f) && (al1 == 1.0f);
        if (!__all_sync(0xffffffffu, nochg)) {
#pragma unroll
            for (int nt = 0; nt < 8; nt++) {
                oacc[nt][0] *= al0; oacc[nt][1] *= al0;
                oacc[nt][2] *= al1; oacc[nt][3] *= al1;
            }
        }
        rs0 += __shfl_xor_sync(0xffffffffu, rs0, 1);
        rs0 += __shfl_xor_sync(0xffffffffu, rs0, 2);
        rs1 += __shfl_xor_sync(0xffffffffu, rs1, 1);
        rs1 += __shfl_xor_sync(0xffffffffu, rs1, 2);
        lr0 = lr0 * al0 + rs0;
        lr1 = lr1 * al1 + rs1;
        mr0 = mn0; mr1 = mn1;

        // ---- O += P V (software-pipelined V-frag loads) ----
        {
            unsigned vf[2][4];
            ldsm_x4_t(vf[0][0], vf[0][1], vf[0][2], vf[0][3], vb);
#pragma unroll
            for (int it = 0; it < 16; it++) {
                const int t = it >> 2, db = it & 3;
                if (it + 1 < 16) {
                    const int t2 = (it + 1) >> 2, db2 = (it + 1) & 3;
                    ldsm_x4_t(vf[(it + 1) & 1][0], vf[(it + 1) & 1][1],
                              vf[(it + 1) & 1][2], vf[(it + 1) & 1][3],
                              vb + (unsigned)((t2 * 16 * FST + db2 * 16) * 2));
                }
                unsigned b0[2] = {vf[it & 1][0], vf[it & 1][1]};
                unsigned b1[2] = {vf[it & 1][2], vf[it & 1][3]};
                mma16816h(oacc[db * 2 + 0], pa[t], b0);
                mma16816h(oacc[db * 2 + 1], pa[t], b1);
            }
        }

        if (++stage >= 3) stage = 0;
    }

    // ---- epilogue: write attention out as fp16 ----
    const float inv0 = 1.0f / lr0;
    const float inv1 = 1.0f / lr1;
    __half* Ch = g_Cf + hoff;
    const int row0 = q0 + wid * 16 + (lane >> 2);
#pragma unroll
    for (int nt = 0; nt < 8; nt++) {
        const int d = nt * 8 + tg * 2;
        *(unsigned*)(Ch + (size_t)row0 * Dmodel + d) =
            packf16(oacc[nt][0] * inv0, oacc[nt][1] * inv0);
        *(unsigned*)(Ch + (size_t)(row0 + 8) * Dmodel + d) =
            packf16(oacc[nt][2] * inv1, oacc[nt][3] * inv1);
    }
}

// ---------------------------------------------------------------------------
extern "C" void kernel_launch(void* const* d_in, const int* in_sizes, int n_in,
                              void* d_out, int out_size)
{
    const float* q  = (const float*)d_in[0];
    const float* k  = (const float*)d_in[1];
    const float* v  = (const float*)d_in[2];
    const float* Wq = (const float*)d_in[3];
    const float* bq = (const float*)d_in[4];
    const float* Wk = (const float*)d_in[5];
    const float* bk = (const float*)d_in[6];
    const float* Wv = (const float*)d_in[7];
    const float* bv = (const float*)d_in[8];
    const float* Wo = (const float*)d_in[9];
    const float* bo = (const float*)d_in[10];
    float* out = (float*)d_out;

    cudaFuncSetAttribute(flash_attn, cudaFuncAttributeMaxDynamicSharedMemorySize, FSMEM);
    cudaFuncSetAttribute(qkv_gemm, cudaFuncAttributeMaxDynamicSharedMemorySize, GSMEM);
    cudaFuncSetAttribute(out_gemm, cudaFuncAttributeMaxDynamicSharedMemorySize, GSMEM);

    conv_all<<<dim3(NELEM / 1024, 1, 7), 256>>>(q, k, v, Wq, Wk, Wv, Wo);

    dim3 gqkv(Dmodel / 128, Mrows / 128, 3);   // 8 x 32 x 3
    qkv_gemm<<<gqkv, 256, GSMEM>>>(bq, bk, bv);

    dim3 gf(Nseq / 128, Bsz * Hh);             // 16 x 32
    flash_attn<<<gf, 256, FSMEM>>>();

    dim3 go(Dmodel / 128, Mrows / 128);        // 8 x 32
    out_gemm<<<go, 256, GSMEM>>>(bo, out);
}

// round 13
// speedup vs baseline: 1.0120x; 1.0120x over previous
#include <cuda_runtime.h>
#include <cuda_fp16.h>

// Problem constants
#define Bsz    2
#define Nseq   2048
#define Dmodel 1024
#define Hh     16
#define DKh    64
#define Mrows  4096
#define NELEM  (Mrows * Dmodel)     // 4,194,304
#define WELEM  (Dmodel * Dmodel)    // 1,048,576
#define SCALE  0.125f
#define QSCALE (0.125f * 1.44269504088896f)   // fold log2(e): softmax in exp2 domain

// ---- mma.sync / ldmatrix / cp.async helpers (base sm_80+ ISA) ----
__device__ __forceinline__ unsigned smem_u32(const void* p) {
    unsigned a;
    asm("{ .reg .u64 t; cvta.to.shared.u64 t, %1; cvt.u32.u64 %0, t; }" : "=r"(a) : "l"(p));
    return a;
}
__device__ __forceinline__ void ldsm_x4(unsigned& r0, unsigned& r1, unsigned& r2, unsigned& r3,
                                        unsigned addr) {
    asm volatile("ldmatrix.sync.aligned.m8n8.x4.shared.b16 {%0,%1,%2,%3}, [%4];"
                 : "=r"(r0), "=r"(r1), "=r"(r2), "=r"(r3) : "r"(addr));
}
__device__ __forceinline__ void ldsm_x4_t(unsigned& r0, unsigned& r1, unsigned& r2, unsigned& r3,
                                          unsigned addr) {
    asm volatile("ldmatrix.sync.aligned.m8n8.x4.trans.shared.b16 {%0,%1,%2,%3}, [%4];"
                 : "=r"(r0), "=r"(r1), "=r"(r2), "=r"(r3) : "r"(addr));
}
__device__ __forceinline__ void mma16816h(float* c, const unsigned* a, const unsigned* b) {
    asm volatile("mma.sync.aligned.m16n8k16.row.col.f32.f16.f16.f32 "
                 "{%0,%1,%2,%3},{%4,%5,%6,%7},{%8,%9},{%0,%1,%2,%3};"
                 : "+f"(c[0]), "+f"(c[1]), "+f"(c[2]), "+f"(c[3])
                 : "r"(a[0]), "r"(a[1]), "r"(a[2]), "r"(a[3]), "r"(b[0]), "r"(b[1]));
}
__device__ __forceinline__ void cpa16(unsigned dst, const void* src) {
    asm volatile("cp.async.cg.shared.global [%0], [%1], 16;" :: "r"(dst), "l"(src));
}
__device__ __forceinline__ void cpa_commit() { asm volatile("cp.async.commit_group;"); }
template<int N> __device__ __forceinline__ void cpa_wait() {
    asm volatile("cp.async.wait_group %0;" :: "n"(N));
}
__device__ __forceinline__ unsigned packf16(float x, float y) {
    __half2 t = __floats2half2_rn(x, y);
    return *reinterpret_cast<unsigned*>(&t);
}
__device__ __forceinline__ unsigned ex2h2(unsigned d) {
    unsigned e;
    asm("ex2.approx.f16x2 %0, %1;" : "=r"(e) : "r"(d));
    return e;
}

// ---- scratch (fp16) ----
__device__ __half g_xf[3 * NELEM];   // converted inputs q,k,v
__device__ __half g_wf[4 * WELEM];   // converted weights Wq,Wk,Wv,Wo
__device__ __half g_pf[3 * NELEM];   // projected Q(pre-scaled),K,V
__device__ __half g_Cf[NELEM];       // attention output

// ---------------------------------------------------------------------------
// Convert kernels: fp32 -> fp16
// ---------------------------------------------------------------------------
__global__ __launch_bounds__(256) void conv_inputs(const float* __restrict__ q,
                                                   const float* __restrict__ k,
                                                   const float* __restrict__ v)
{
    const int z = blockIdx.z;
    const float* src = (z == 0) ? q : (z == 1) ? k : v;
    __half* dst = g_xf + (size_t)z * NELEM;
    const size_t i = ((size_t)blockIdx.x * 256 + threadIdx.x) * 4;
    float4 f = *(const float4*)(src + i);
    uint2 o;
    o.x = packf16(f.x, f.y);
    o.y = packf16(f.z, f.w);
    *(uint2*)(dst + i) = o;
}

__global__ __launch_bounds__(256) void conv_weights(const float* __restrict__ wq,
                                                    const float* __restrict__ wk,
                                                    const float* __restrict__ wv,
                                                    const float* __restrict__ wo)
{
    const int z = blockIdx.z;
    const float* src = (z == 0) ? wq : (z == 1) ? wk : (z == 2) ? wv : wo;
    __half* dst = g_wf + (size_t)z * WELEM;
    const size_t i = ((size_t)blockIdx.x * 256 + threadIdx.x) * 4;
    float4 f = *(const float4*)(src + i);
    uint2 o;
    o.x = packf16(f.x, f.y);
    o.y = packf16(f.z, f.w);
    *(uint2*)(dst + i) = o;
}

// ---------------------------------------------------------------------------
// fp16 single-pass HMMA GEMM, cp.async 2-stage: C = X @ W^T + bias
// Tile 128x128, Kc=64, 8 warps (2x4), warp tile 64x32.  (round-11 proven)
// ---------------------------------------------------------------------------
#define KC 64
#define NCH (Dmodel / KC)     // 16
#define GST 72
#define GBUF (128 * GST * 2)  // 18432 B
#define GSTAGE (2 * GBUF)     // 36864 B
#define GSMEM (2 * GSTAGE)    // 73728 B

__device__ __forceinline__ void g_load(unsigned sbase, int stage,
                                       const __half* Xf, const __half* Wf,
                                       int m0, int n0, int k0, int tid)
{
    const int row = tid >> 1;
    const int co  = (tid & 1) * 32;
    const unsigned dst0 = sbase + (unsigned)(stage * GSTAGE + row * 144 + (tid & 1) * 64);
    const size_t asrc = (size_t)(m0 + row) * Dmodel + k0 + co;
    const size_t bsrc = (size_t)(n0 + row) * Dmodel + k0 + co;
#pragma unroll
    for (int j = 0; j < 4; j++) {
        cpa16(dst0 + j * 16,        Xf + asrc + j * 8);
        cpa16(dst0 + GBUF + j * 16, Wf + bsrc + j * 8);
    }
}

__device__ __forceinline__ void gemm_body(const __half* __restrict__ Xf,
                                          const __half* __restrict__ Wf,
                                          const float* __restrict__ bias,
                                          __half* C16, float* Cf, float cscale)
{
    extern __shared__ __align__(16) char smg[];
    const unsigned sbase = smem_u32(smg);

    const int tid  = threadIdx.x;
    const int wid  = tid >> 5;
    const int lane = tid & 31;
    const int wm   = wid >> 2;
    const int wn   = wid & 3;
    const int m0   = blockIdx.y * 128;
    const int n0   = blockIdx.x * 128;

    float acc[4][4][4];
#pragma unroll
    for (int mt = 0; mt < 4; mt++)
#pragma unroll
        for (int nt = 0; nt < 4; nt++)
#pragma unroll
            for (int i = 0; i < 4; i++) acc[mt][nt][i] = 0.0f;

    const unsigned a_off = (unsigned)(((wm * 64 + (lane & 15)) * GST + (lane >> 4) * 8) * 2);
    const unsigned b_off = (unsigned)(((wn * 32 + (lane & 15)) * GST + (lane >> 4) * 8) * 2);

    g_load(sbase, 0, Xf, Wf, m0, n0, 0, tid);
    cpa_commit();
    g_load(sbase, 1, Xf, Wf, m0, n0, KC, tid);
    cpa_commit();
    cpa_wait<1>();
    __syncthreads();

    for (int ch = 0; ch < NCH; ch++) {
        const unsigned st = sbase + (unsigned)((ch & 1) * GSTAGE);
        const unsigned abase = st + a_off;
        const unsigned bbase = st + GBUF + b_off;

#pragma unroll
        for (int ks = 0; ks < 4; ks++) {
            const unsigned koff = (unsigned)(ks * 16 * 2);
            unsigned bf[4][2];
#pragma unroll
            for (int np = 0; np < 2; np++) {
                unsigned r0, r1, r2, r3;
                ldsm_x4(r0, r1, r2, r3,
                        bbase + koff + (unsigned)(np * 16 * GST * 2));
                bf[np * 2 + 0][0] = r0; bf[np * 2 + 0][1] = r2;
                bf[np * 2 + 1][0] = r1; bf[np * 2 + 1][1] = r3;
            }
            unsigned af[4][4];
#pragma unroll
            for (int mt = 0; mt < 4; mt++)
                ldsm_x4(af[mt][0], af[mt][1], af[mt][2], af[mt][3],
                        abase + koff + (unsigned)(mt * 16 * GST * 2));
#pragma unroll
            for (int mt = 0; mt < 4; mt++)
#pragma unroll
                for (int nt = 0; nt < 4; nt++)
                    mma16816h(acc[mt][nt], af[mt], bf[nt]);
        }
        __syncthreads();

        if (ch + 1 < NCH) {
            if (ch + 2 < NCH) {
                g_load(sbase, ch & 1, Xf, Wf, m0, n0, (ch + 2) * KC, tid);
                cpa_commit();
                cpa_wait<1>();
            } else {
                cpa_wait<0>();
            }
            __syncthreads();
        }
    }

    const int g   = lane >> 2;
    const int tig = lane & 3;
#pragma unroll
    for (int mt = 0; mt < 4; mt++) {
        const int r0 = m0 + wm * 64 + mt * 16 + g;
#pragma unroll
        for (int nt = 0; nt < 4; nt++) {
            const int cidx = n0 + wn * 32 + nt * 8 + tig * 2;
            const float2 bv = *(const float2*)(bias + cidx);
            const float x0 = acc[mt][nt][0] + bv.x;
            const float x1 = acc[mt][nt][1] + bv.y;
            const float x2 = acc[mt][nt][2] + bv.x;
            const float x3 = acc[mt][nt][3] + bv.y;
            if (Cf) {
                *(float2*)(Cf + (size_t)r0 * Dmodel + cidx) = make_float2(x0, x1);
                *(float2*)(Cf + (size_t)(r0 + 8) * Dmodel + cidx) = make_float2(x2, x3);
            } else {
                *(unsigned*)(C16 + (size_t)r0 * Dmodel + cidx) =
                    packf16(x0 * cscale, x1 * cscale);
                *(unsigned*)(C16 + (size_t)(r0 + 8) * Dmodel + cidx) =
                    packf16(x2 * cscale, x3 * cscale);
            }
        }
    }
}

__global__ __launch_bounds__(256, 2) void qkv_gemm(const float* __restrict__ bq,
                                                   const float* __restrict__ bk,
                                                   const float* __restrict__ bv)
{
    const int z = blockIdx.z;
    const float* bias = (z == 0) ? bq : (z == 1) ? bk : bv;
    const float cs = (z == 0) ? QSCALE : 1.0f;
    gemm_body(g_xf + (size_t)z * NELEM, g_wf + (size_t)z * WELEM,
              bias, g_pf + (size_t)z * NELEM, nullptr, cs);
}

__global__ __launch_bounds__(256, 2) void out_gemm(const float* __restrict__ bo,
                                                   float* __restrict__ out)
{
    gemm_body(g_Cf, g_wf + (size_t)3 * WELEM, bo, nullptr, out, 1.0f);
}

// ---------------------------------------------------------------------------
// Flash attention, fp16 HMMA, cp.async 2-stage K/V pipeline.
// NOW: 64 q-rows / 128 threads per CTA -> 4 CTAs/SM for phase overlap.
// half2 softmax via ex2.approx.f16x2 (output IS the PV fragment).
// ---------------------------------------------------------------------------
#define FST 72
#define QBUF  (64 * FST * 2)      // 9216
#define KVBUF (64 * FST * 2)      // 9216
#define KVSTAGE (2 * KVBUF)       // 18432
#define FSMEM (QBUF + 2 * KVSTAGE)   // 46080

__device__ __forceinline__ void f_loadKV(unsigned kvbase, int stage, int jt,
                                         const __half* Kf, const __half* Vf, int tid)
{
    // 128 threads: each loads 64B of K and 64B of V
    const int row = tid >> 1;              // 0..63
    const int c2  = tid & 1;               // half-row selector (32 halves)
    const unsigned dst0 = kvbase + (unsigned)(stage * KVSTAGE + row * 144 + c2 * 64);
    const size_t src = (size_t)(jt + row) * Dmodel + c2 * 32;
#pragma unroll
    for (int j = 0; j < 4; j++) {
        cpa16(dst0 + j * 16,         Kf + src + j * 8);
        cpa16(dst0 + KVBUF + j * 16, Vf + src + j * 8);
    }
}

__global__ __launch_bounds__(128, 4) void flash_attn()
{
    extern __shared__ __align__(16) char smf[];
    const unsigned sbase  = smem_u32(smf);
    const unsigned kvbase = sbase + QBUF;

    const int tid  = threadIdx.x;          // 0..127
    const int wid  = tid >> 5;             // 0..3
    const int lane = tid & 31;
    const int tg   = lane & 3;
    const int bh   = blockIdx.y;
    const int b    = bh >> 4;
    const int h    = bh & 15;
    const int q0   = blockIdx.x * 64;

    const size_t hoff = (size_t)b * Nseq * Dmodel + h * DKh;
    const __half* Qf = g_pf + hoff;
    const __half* Kf = g_pf + NELEM + hoff;
    const __half* Vf = g_pf + 2 * NELEM + hoff;

    // prologue: Q (64 rows) + KV tiles 0,1
    {
        const int row = tid >> 1;          // 0..63
        const int c2  = tid & 1;
        const unsigned dq = sbase + (unsigned)(row * 144 + c2 * 64);
        const size_t src = (size_t)(q0 + row) * Dmodel + c2 * 32;
#pragma unroll
        for (int j = 0; j < 4; j++)
            cpa16(dq + j * 16, Qf + src + j * 8);
    }
    f_loadKV(kvbase, 0, 0, Kf, Vf, tid);
    cpa_commit();
    f_loadKV(kvbase, 1, 64, Kf, Vf, tid);
    cpa_commit();
    cpa_wait<1>();
    __syncthreads();

    // persistent Q fragments (warp wid owns rows wid*16..wid*16+15)
    const unsigned qa = sbase +
        (unsigned)(((wid * 16 + (lane & 15)) * FST + (lane >> 4) * 8) * 2);
    unsigned aq[4][4];
#pragma unroll
    for (int ks = 0; ks < 4; ks++)
        ldsm_x4(aq[ks][0], aq[ks][1], aq[ks][2], aq[ks][3], qa + ks * 32);

    const unsigned kb_off = (unsigned)(((lane & 15) * FST + (lane >> 4) * 8) * 2);

    float oacc[8][4];
#pragma unroll
    for (int nt = 0; nt < 8; nt++)
#pragma unroll
        for (int i = 0; i < 4; i++) oacc[nt][i] = 0.0f;
    float mr0 = -1e30f, mr1 = -1e30f, lr0 = 0.0f, lr1 = 0.0f;

    const int NT = Nseq / 64;   // 32
    for (int jt = 0; jt < NT; jt++) {
        const unsigned st = kvbase + (unsigned)((jt & 1) * KVSTAGE);
        const unsigned kb = st + kb_off;
        const unsigned vb = st + KVBUF + kb_off;

        // ---- S = Q K^T (log2 domain; scale pre-folded into Q) ----
        float sacc[8][4];
#pragma unroll
        for (int nt = 0; nt < 8; nt++)
#pragma unroll
            for (int i = 0; i < 4; i++) sacc[nt][i] = 0.0f;

        {
            unsigned kf[2][4];
            ldsm_x4(kf[0][0], kf[0][1], kf[0][2], kf[0][3], kb);
#pragma unroll
            for (int it = 0; it < 16; it++) {
                const int ks = it >> 2, jb = it & 3;
                if (it + 1 < 16) {
                    const int ks2 = (it + 1) >> 2, jb2 = (it + 1) & 3;
                    ldsm_x4(kf[(it + 1) & 1][0], kf[(it + 1) & 1][1],
                            kf[(it + 1) & 1][2], kf[(it + 1) & 1][3],
                            kb + (unsigned)((jb2 * 16 * FST + ks2 * 16) * 2));
                }
                unsigned bf0[2] = {kf[it & 1][0], kf[it & 1][2]};
                unsigned bf1[2] = {kf[it & 1][1], kf[it & 1][3]};
                mma16816h(sacc[jb * 2 + 0], aq[ks], bf0);
                mma16816h(sacc[jb * 2 + 1], aq[ks], bf1);
            }
        }

        // ---- online softmax (half2 exp; ex2 output IS the PV fragment) ----
        float mx0 = -1e30f, mx1 = -1e30f;
#pragma unroll
        for (int nt = 0; nt < 8; nt++) {
            mx0 = fmaxf(mx0, fmaxf(sacc[nt][0], sacc[nt][1]));
            mx1 = fmaxf(mx1, fmaxf(sacc[nt][2], sacc[nt][3]));
        }
        mx0 = fmaxf(mx0, __shfl_xor_sync(0xffffffffu, mx0, 1));
        mx0 = fmaxf(mx0, __shfl_xor_sync(0xffffffffu, mx0, 2));
        mx1 = fmaxf(mx1, __shfl_xor_sync(0xffffffffu, mx1, 1));
        mx1 = fmaxf(mx1, __shfl_xor_sync(0xffffffffu, mx1, 2));
        const float mn0 = fmaxf(mr0, mx0);
        const float mn1 = fmaxf(mr1, mx1);
        const float al0 = exp2f(mr0 - mn0);
        const float al1 = exp2f(mr1 - mn1);

        unsigned pa[4][4];
        float rs0 = 0.0f, rs1 = 0.0f;
#pragma unroll
        for (int grp = 0; grp < 2; grp++) {
            __half2 a01 = __float2half2_rn(0.0f);
            __half2 a23 = __float2half2_rn(0.0f);
#pragma unroll
            for (int k2 = 0; k2 < 4; k2++) {
                const int nt = grp * 4 + k2;
                const unsigned e01 = ex2h2(packf16(sacc[nt][0] - mn0, sacc[nt][1] - mn0));
                const unsigned e23 = ex2h2(packf16(sacc[nt][2] - mn1, sacc[nt][3] - mn1));
                const int t = nt >> 1;
                if ((nt & 1) == 0) { pa[t][0] = e01; pa[t][1] = e23; }
                else               { pa[t][2] = e01; pa[t][3] = e23; }
                a01 = __hadd2(a01, *reinterpret_cast<const __half2*>(&e01));
                a23 = __hadd2(a23, *reinterpret_cast<const __half2*>(&e23));
            }
            const float2 f01 = __half22float2(a01);
            const float2 f23 = __half22float2(a23);
            rs0 += f01.x + f01.y;
            rs1 += f23.x + f23.y;
        }
        const bool nochg = (al0 == 1.0f) && (al1 == 1.0f);
        if (!__all_sync(0xffffffffu, nochg)) {
#pragma unroll
            for (int nt = 0; nt < 8; nt++) {
                oacc[nt][0] *= al0; oacc[nt][1] *= al0;
                oacc[nt][2] *= al1; oacc[nt][3] *= al1;
            }
        }
        rs0 += __shfl_xor_sync(0xffffffffu, rs0, 1);
        rs0 += __shfl_xor_sync(0xffffffffu, rs0, 2);
        rs1 += __shfl_xor_sync(0xffffffffu, rs1, 1);
        rs1 += __shfl_xor_sync(0xffffffffu, rs1, 2);
        lr0 = lr0 * al0 + rs0;
        lr1 = lr1 * al1 + rs1;
        mr0 = mn0; mr1 = mn1;

        // ---- O += P V (software-pipelined V-frag loads) ----
        {
            unsigned vf[2][4];
            ldsm_x4_t(vf[0][0], vf[0][1], vf[0][2], vf[0][3], vb);
#pragma unroll
            for (int it = 0; it < 16; it++) {
                const int t = it >> 2, db = it & 3;
                if (it + 1 < 16) {
                    const int t2 = (it + 1) >> 2, db2 = (it + 1) & 3;
                    ldsm_x4_t(vf[(it + 1) & 1][0], vf[(it + 1) & 1][1],
                              vf[(it + 1) & 1][2], vf[(it + 1) & 1][3],
                              vb + (unsigned)((t2 * 16 * FST + db2 * 16) * 2));
                }
                unsigned b0[2] = {vf[it & 1][0], vf[it & 1][1]};
                unsigned b1[2] = {vf[it & 1][2], vf[it & 1][3]};
                mma16816h(oacc[db * 2 + 0], pa[t], b0);
                mma16816h(oacc[db * 2 + 1], pa[t], b1);
            }
        }

        __syncthreads();
        if (jt + 1 < NT) {
            if (jt + 2 < NT) {
                f_loadKV(kvbase, jt & 1, (jt + 2) * 64, Kf, Vf, tid);
                cpa_commit();
                cpa_wait<1>();
            } else {
                cpa_wait<0>();
            }
            __syncthreads();
        }
    }

    // ---- epilogue: write attention out as fp16 ----
    const float inv0 = 1.0f / lr0;
    const float inv1 = 1.0f / lr1;
    __half* Ch = g_Cf + hoff;
    const int row0 = q0 + wid * 16 + (lane >> 2);
#pragma unroll
    for (int nt = 0; nt < 8; nt++) {
        const int d = nt * 8 + tg * 2;
        *(unsigned*)(Ch + (size_t)row0 * Dmodel + d) =
            packf16(oacc[nt][0] * inv0, oacc[nt][1] * inv0);
        *(unsigned*)(Ch + (size_t)(row0 + 8) * Dmodel + d) =
            packf16(oacc[nt][2] * inv1, oacc[nt][3] * inv1);
    }
}

// ---------------------------------------------------------------------------
extern "C" void kernel_launch(void* const* d_in, const int* in_sizes, int n_in,
                              void* d_out, int out_size)
{
    const float* q  = (const float*)d_in[0];
    const float* k  = (const float*)d_in[1];
    const float* v  = (const float*)d_in[2];
    const float* Wq = (const float*)d_in[3];
    const float* bq = (const float*)d_in[4];
    const float* Wk = (const float*)d_in[5];
    const float* bk = (const float*)d_in[6];
    const float* Wv = (const float*)d_in[7];
    const float* bv = (const float*)d_in[8];
    const float* Wo = (const float*)d_in[9];
    const float* bo = (const float*)d_in[10];
    float* out = (float*)d_out;

    cudaFuncSetAttribute(flash_attn, cudaFuncAttributeMaxDynamicSharedMemorySize, FSMEM);
    cudaFuncSetAttribute(qkv_gemm, cudaFuncAttributeMaxDynamicSharedMemorySize, GSMEM);
    cudaFuncSetAttribute(out_gemm, cudaFuncAttributeMaxDynamicSharedMemorySize, GSMEM);

    conv_inputs<<<dim3(NELEM / 1024, 1, 3), 256>>>(q, k, v);
    conv_weights<<<dim3(WELEM / 1024, 1, 4), 256>>>(Wq, Wk, Wv, Wo);

    dim3 gqkv(Dmodel / 128, Mrows / 128, 3);   // 8 x 32 x 3
    qkv_gemm<<<gqkv, 256, GSMEM>>>(bq, bk, bv);

    dim3 gf(Nseq / 64, Bsz * Hh);              // 32 x 32
    flash_attn<<<gf, 128, FSMEM>>>();

    dim3 go(Dmodel / 128, Mrows / 128);        // 8 x 32
    out_gemm<<<go, 256, GSMEM>>>(bo, out);
}

// round 14
// speedup vs baseline: 1.0465x; 1.0341x over previous
#include <cuda_runtime.h>
#include <cuda_fp16.h>

// Problem constants
#define Bsz    2
#define Nseq   2048
#define Dmodel 1024
#define Hh     16
#define DKh    64
#define Mrows  4096
#define NELEM  (Mrows * Dmodel)     // 4,194,304
#define WELEM  (Dmodel * Dmodel)    // 1,048,576
#define SCALE  0.125f
#define QSCALE (0.125f * 1.44269504088896f)   // fold log2(e): softmax in exp2 domain

// ---- mma.sync / ldmatrix / cp.async helpers (base sm_80+ ISA) ----
__device__ __forceinline__ unsigned smem_u32(const void* p) {
    unsigned a;
    asm("{ .reg .u64 t; cvta.to.shared.u64 t, %1; cvt.u32.u64 %0, t; }" : "=r"(a) : "l"(p));
    return a;
}
__device__ __forceinline__ void ldsm_x4(unsigned& r0, unsigned& r1, unsigned& r2, unsigned& r3,
                                        unsigned addr) {
    asm volatile("ldmatrix.sync.aligned.m8n8.x4.shared.b16 {%0,%1,%2,%3}, [%4];"
                 : "=r"(r0), "=r"(r1), "=r"(r2), "=r"(r3) : "r"(addr));
}
__device__ __forceinline__ void ldsm_x4_t(unsigned& r0, unsigned& r1, unsigned& r2, unsigned& r3,
                                          unsigned addr) {
    asm volatile("ldmatrix.sync.aligned.m8n8.x4.trans.shared.b16 {%0,%1,%2,%3}, [%4];"
                 : "=r"(r0), "=r"(r1), "=r"(r2), "=r"(r3) : "r"(addr));
}
__device__ __forceinline__ void mma16816h(float* c, const unsigned* a, const unsigned* b) {
    asm volatile("mma.sync.aligned.m16n8k16.row.col.f32.f16.f16.f32 "
                 "{%0,%1,%2,%3},{%4,%5,%6,%7},{%8,%9},{%0,%1,%2,%3};"
                 : "+f"(c[0]), "+f"(c[1]), "+f"(c[2]), "+f"(c[3])
                 : "r"(a[0]), "r"(a[1]), "r"(a[2]), "r"(a[3]), "r"(b[0]), "r"(b[1]));
}
__device__ __forceinline__ void cpa16(unsigned dst, const void* src) {
    asm volatile("cp.async.cg.shared.global [%0], [%1], 16;" :: "r"(dst), "l"(src));
}
__device__ __forceinline__ void cpa_commit() { asm volatile("cp.async.commit_group;"); }
template<int N> __device__ __forceinline__ void cpa_wait() {
    asm volatile("cp.async.wait_group %0;" :: "n"(N));
}
__device__ __forceinline__ unsigned packf16(float x, float y) {
    __half2 t = __floats2half2_rn(x, y);
    return *reinterpret_cast<unsigned*>(&t);
}
__device__ __forceinline__ unsigned ex2h2(unsigned d) {
    unsigned e;
    asm("ex2.approx.f16x2 %0, %1;" : "=r"(e) : "r"(d));
    return e;
}

// ---- scratch (fp16) ----
__device__ __half g_xf[3 * NELEM];   // converted inputs q,k,v
__device__ __half g_wf[4 * WELEM];   // converted weights Wq,Wk,Wv,Wo
__device__ __half g_pf[3 * NELEM];   // projected Q(pre-scaled),K,V
__device__ __half g_Cf[NELEM];       // attention output

// ---------------------------------------------------------------------------
// Convert kernels: fp32 -> fp16  (round-11 proven)
// ---------------------------------------------------------------------------
__global__ __launch_bounds__(256) void conv_inputs(const float* __restrict__ q,
                                                   const float* __restrict__ k,
                                                   const float* __restrict__ v)
{
    const int z = blockIdx.z;
    const float* src = (z == 0) ? q : (z == 1) ? k : v;
    __half* dst = g_xf + (size_t)z * NELEM;
    const size_t i = ((size_t)blockIdx.x * 256 + threadIdx.x) * 4;
    float4 f = *(const float4*)(src + i);
    uint2 o;
    o.x = packf16(f.x, f.y);
    o.y = packf16(f.z, f.w);
    *(uint2*)(dst + i) = o;
}

__global__ __launch_bounds__(256) void conv_weights(const float* __restrict__ wq,
                                                    const float* __restrict__ wk,
                                                    const float* __restrict__ wv,
                                                    const float* __restrict__ wo)
{
    const int z = blockIdx.z;
    const float* src = (z == 0) ? wq : (z == 1) ? wk : (z == 2) ? wv : wo;
    __half* dst = g_wf + (size_t)z * WELEM;
    const size_t i = ((size_t)blockIdx.x * 256 + threadIdx.x) * 4;
    float4 f = *(const float4*)(src + i);
    uint2 o;
    o.x = packf16(f.x, f.y);
    o.y = packf16(f.z, f.w);
    *(uint2*)(dst + i) = o;
}

// ---------------------------------------------------------------------------
// fp16 single-pass HMMA GEMM, cp.async 2-stage (round-11 proven)
// ---------------------------------------------------------------------------
#define KC 64
#define NCH (Dmodel / KC)     // 16
#define GST 72
#define GBUF (128 * GST * 2)  // 18432 B
#define GSTAGE (2 * GBUF)     // 36864 B
#define GSMEM (2 * GSTAGE)    // 73728 B

__device__ __forceinline__ void g_load(unsigned sbase, int stage,
                                       const __half* Xf, const __half* Wf,
                                       int m0, int n0, int k0, int tid)
{
    const int row = tid >> 1;
    const int co  = (tid & 1) * 32;
    const unsigned dst0 = sbase + (unsigned)(stage * GSTAGE + row * 144 + (tid & 1) * 64);
    const size_t asrc = (size_t)(m0 + row) * Dmodel + k0 + co;
    const size_t bsrc = (size_t)(n0 + row) * Dmodel + k0 + co;
#pragma unroll
    for (int j = 0; j < 4; j++) {
        cpa16(dst0 + j * 16,        Xf + asrc + j * 8);
        cpa16(dst0 + GBUF + j * 16, Wf + bsrc + j * 8);
    }
}

__device__ __forceinline__ void gemm_body(const __half* __restrict__ Xf,
                                          const __half* __restrict__ Wf,
                                          const float* __restrict__ bias,
                                          __half* C16, float* Cf, float cscale)
{
    extern __shared__ __align__(16) char smg[];
    const unsigned sbase = smem_u32(smg);

    const int tid  = threadIdx.x;
    const int wid  = tid >> 5;
    const int lane = tid & 31;
    const int wm   = wid >> 2;
    const int wn   = wid & 3;
    const int m0   = blockIdx.y * 128;
    const int n0   = blockIdx.x * 128;

    float acc[4][4][4];
#pragma unroll
    for (int mt = 0; mt < 4; mt++)
#pragma unroll
        for (int nt = 0; nt < 4; nt++)
#pragma unroll
            for (int i = 0; i < 4; i++) acc[mt][nt][i] = 0.0f;

    const unsigned a_off = (unsigned)(((wm * 64 + (lane & 15)) * GST + (lane >> 4) * 8) * 2);
    const unsigned b_off = (unsigned)(((wn * 32 + (lane & 15)) * GST + (lane >> 4) * 8) * 2);

    g_load(sbase, 0, Xf, Wf, m0, n0, 0, tid);
    cpa_commit();
    g_load(sbase, 1, Xf, Wf, m0, n0, KC, tid);
    cpa_commit();
    cpa_wait<1>();
    __syncthreads();

    for (int ch = 0; ch < NCH; ch++) {
        const unsigned st = sbase + (unsigned)((ch & 1) * GSTAGE);
        const unsigned abase = st + a_off;
        const unsigned bbase = st + GBUF + b_off;

#pragma unroll
        for (int ks = 0; ks < 4; ks++) {
            const unsigned koff = (unsigned)(ks * 16 * 2);
            unsigned bf[4][2];
#pragma unroll
            for (int np = 0; np < 2; np++) {
                unsigned r0, r1, r2, r3;
                ldsm_x4(r0, r1, r2, r3,
                        bbase + koff + (unsigned)(np * 16 * GST * 2));
                bf[np * 2 + 0][0] = r0; bf[np * 2 + 0][1] = r2;
                bf[np * 2 + 1][0] = r1; bf[np * 2 + 1][1] = r3;
            }
            unsigned af[4][4];
#pragma unroll
            for (int mt = 0; mt < 4; mt++)
                ldsm_x4(af[mt][0], af[mt][1], af[mt][2], af[mt][3],
                        abase + koff + (unsigned)(mt * 16 * GST * 2));
#pragma unroll
            for (int mt = 0; mt < 4; mt++)
#pragma unroll
                for (int nt = 0; nt < 4; nt++)
                    mma16816h(acc[mt][nt], af[mt], bf[nt]);
        }
        __syncthreads();

        if (ch + 1 < NCH) {
            if (ch + 2 < NCH) {
                g_load(sbase, ch & 1, Xf, Wf, m0, n0, (ch + 2) * KC, tid);
                cpa_commit();
                cpa_wait<1>();
            } else {
                cpa_wait<0>();
            }
            __syncthreads();
        }
    }

    const int g   = lane >> 2;
    const int tig = lane & 3;
#pragma unroll
    for (int mt = 0; mt < 4; mt++) {
        const int r0 = m0 + wm * 64 + mt * 16 + g;
#pragma unroll
        for (int nt = 0; nt < 4; nt++) {
            const int cidx = n0 + wn * 32 + nt * 8 + tig * 2;
            const float2 bv = *(const float2*)(bias + cidx);
            const float x0 = acc[mt][nt][0] + bv.x;
            const float x1 = acc[mt][nt][1] + bv.y;
            const float x2 = acc[mt][nt][2] + bv.x;
            const float x3 = acc[mt][nt][3] + bv.y;
            if (Cf) {
                *(float2*)(Cf + (size_t)r0 * Dmodel + cidx) = make_float2(x0, x1);
                *(float2*)(Cf + (size_t)(r0 + 8) * Dmodel + cidx) = make_float2(x2, x3);
            } else {
                *(unsigned*)(C16 + (size_t)r0 * Dmodel + cidx) =
                    packf16(x0 * cscale, x1 * cscale);
                *(unsigned*)(C16 + (size_t)(r0 + 8) * Dmodel + cidx) =
                    packf16(x2 * cscale, x3 * cscale);
            }
        }
    }
}

__global__ __launch_bounds__(256, 2) void qkv_gemm(const float* __restrict__ bq,
                                                   const float* __restrict__ bk,
                                                   const float* __restrict__ bv)
{
    const int z = blockIdx.z;
    const float* bias = (z == 0) ? bq : (z == 1) ? bk : bv;
    const float cs = (z == 0) ? QSCALE : 1.0f;
    gemm_body(g_xf + (size_t)z * NELEM, g_wf + (size_t)z * WELEM,
              bias, g_pf + (size_t)z * NELEM, nullptr, cs);
}

__global__ __launch_bounds__(256, 2) void out_gemm(const float* __restrict__ bo,
                                                   float* __restrict__ out)
{
    gemm_body(g_Cf, g_wf + (size_t)3 * WELEM, bo, nullptr, out, 1.0f);
}

// ---------------------------------------------------------------------------
// Flash attention, fp16 HMMA, cp.async 2-stage K/V pipeline.
// 4 warps x 32 q-rows (128 threads, 128 q-rows/CTA): K/V fragments reused by
// 2 m-tiles -> smem LDSM bytes per FLOP halved vs 8x16 layout.
// half2 softmax via ex2.approx.f16x2 (output IS the PV fragment).
// ---------------------------------------------------------------------------
#define FST 72
#define QBUF  (128 * FST * 2)     // 18432
#define KVBUF (64 * FST * 2)      // 9216
#define KVSTAGE (2 * KVBUF)       // 18432
#define FSMEM (QBUF + 2 * KVSTAGE)   // 55296

__device__ __forceinline__ void f_loadKV(unsigned kvbase, int stage, int jt,
                                         const __half* Kf, const __half* Vf, int tid)
{
    // 128 threads: each loads 64B of K and 64B of V
    const int row = tid >> 1;              // 0..63
    const int c2  = tid & 1;
    const unsigned dst0 = kvbase + (unsigned)(stage * KVSTAGE + row * 144 + c2 * 64);
    const size_t src = (size_t)(jt + row) * Dmodel + c2 * 32;
#pragma unroll
    for (int j = 0; j < 4; j++) {
        cpa16(dst0 + j * 16,         Kf + src + j * 8);
        cpa16(dst0 + KVBUF + j * 16, Vf + src + j * 8);
    }
}

__global__ __launch_bounds__(128, 2) void flash_attn()
{
    extern __shared__ __align__(16) char smf[];
    const unsigned sbase  = smem_u32(smf);
    const unsigned kvbase = sbase + QBUF;

    const int tid  = threadIdx.x;          // 0..127
    const int wid  = tid >> 5;             // 0..3
    const int lane = tid & 31;
    const int tg   = lane & 3;
    const int bh   = blockIdx.y;
    const int b    = bh >> 4;
    const int h    = bh & 15;
    const int q0   = blockIdx.x * 128;

    const size_t hoff = (size_t)b * Nseq * Dmodel + h * DKh;
    const __half* Qf = g_pf + hoff;
    const __half* Kf = g_pf + NELEM + hoff;
    const __half* Vf = g_pf + 2 * NELEM + hoff;

    // prologue: Q (128 rows; 1 thread per row) + KV tiles 0,1
    {
        const unsigned dq = sbase + (unsigned)(tid * 144);
        const __half* src = Qf + (size_t)(q0 + tid) * Dmodel;
#pragma unroll
        for (int j = 0; j < 8; j++)
            cpa16(dq + j * 16, src + j * 8);
    }
    f_loadKV(kvbase, 0, 0, Kf, Vf, tid);
    cpa_commit();
    f_loadKV(kvbase, 1, 64, Kf, Vf, tid);
    cpa_commit();
    cpa_wait<1>();
    __syncthreads();

    // persistent Q fragments: warp owns rows wid*32 .. wid*32+31 (2 m-tiles)
    unsigned aq[2][4][4];
#pragma unroll
    for (int mt = 0; mt < 2; mt++) {
        const unsigned qa = sbase +
            (unsigned)(((wid * 32 + mt * 16 + (lane & 15)) * FST + (lane >> 4) * 8) * 2);
#pragma unroll
        for (int ks = 0; ks < 4; ks++)
            ldsm_x4(aq[mt][ks][0], aq[mt][ks][1], aq[mt][ks][2], aq[mt][ks][3],
                    qa + ks * 32);
    }

    const unsigned kb_off = (unsigned)(((lane & 15) * FST + (lane >> 4) * 8) * 2);

    float oacc[2][8][4];
#pragma unroll
    for (int mt = 0; mt < 2; mt++)
#pragma unroll
        for (int nt = 0; nt < 8; nt++)
#pragma unroll
            for (int i = 0; i < 4; i++) oacc[mt][nt][i] = 0.0f;
    float mr[4] = {-1e30f, -1e30f, -1e30f, -1e30f};
    float lr[4] = {0.0f, 0.0f, 0.0f, 0.0f};

    const int NT = Nseq / 64;   // 32
    for (int jt = 0; jt < NT; jt++) {
        const unsigned st = kvbase + (unsigned)((jt & 1) * KVSTAGE);
        const unsigned kb = st + kb_off;
        const unsigned vb = st + KVBUF + kb_off;

        // ---- S = Q K^T (log2 domain): 16 K-LDSM, 64 MMAs (frag reuse x2) ----
        float sacc[2][8][4];
#pragma unroll
        for (int mt = 0; mt < 2; mt++)
#pragma unroll
            for (int nt = 0; nt < 8; nt++)
#pragma unroll
                for (int i = 0; i < 4; i++) sacc[mt][nt][i] = 0.0f;

#pragma unroll
        for (int ks = 0; ks < 4; ks++) {
#pragma unroll
            for (int jb = 0; jb < 4; jb++) {
                unsigned r0, r1, r2, r3;
                ldsm_x4(r0, r1, r2, r3,
                        kb + (unsigned)((jb * 16 * FST + ks * 16) * 2));
                unsigned bf0[2] = {r0, r2};
                unsigned bf1[2] = {r1, r3};
#pragma unroll
                for (int mt = 0; mt < 2; mt++) {
                    mma16816h(sacc[mt][jb * 2 + 0], aq[mt][ks], bf0);
                    mma16816h(sacc[mt][jb * 2 + 1], aq[mt][ks], bf1);
                }
            }
        }

        // ---- online softmax (half2 exp; 4 row-stats per thread) ----
        float mx[4] = {-1e30f, -1e30f, -1e30f, -1e30f};
#pragma unroll
        for (int mt = 0; mt < 2; mt++)
#pragma unroll
            for (int nt = 0; nt < 8; nt++) {
                mx[mt * 2 + 0] = fmaxf(mx[mt * 2 + 0],
                                       fmaxf(sacc[mt][nt][0], sacc[mt][nt][1]));
                mx[mt * 2 + 1] = fmaxf(mx[mt * 2 + 1],
                                       fmaxf(sacc[mt][nt][2], sacc[mt][nt][3]));
            }
        float mn[4], al[4];
#pragma unroll
        for (int s = 0; s < 4; s++) {
            mx[s] = fmaxf(mx[s], __shfl_xor_sync(0xffffffffu, mx[s], 1));
            mx[s] = fmaxf(mx[s], __shfl_xor_sync(0xffffffffu, mx[s], 2));
            mn[s] = fmaxf(mr[s], mx[s]);
            al[s] = exp2f(mr[s] - mn[s]);
        }

        unsigned pa[2][4][4];
        float rs[4] = {0.0f, 0.0f, 0.0f, 0.0f};
#pragma unroll
        for (int mt = 0; mt < 2; mt++) {
#pragma unroll
            for (int grp = 0; grp < 2; grp++) {
                __half2 a01 = __float2half2_rn(0.0f);
                __half2 a23 = __float2half2_rn(0.0f);
#pragma unroll
                for (int k2 = 0; k2 < 4; k2++) {
                    const int nt = grp * 4 + k2;
                    const unsigned e01 = ex2h2(packf16(sacc[mt][nt][0] - mn[mt * 2],
                                                       sacc[mt][nt][1] - mn[mt * 2]));
                    const unsigned e23 = ex2h2(packf16(sacc[mt][nt][2] - mn[mt * 2 + 1],
                                                       sacc[mt][nt][3] - mn[mt * 2 + 1]));
                    const int t = nt >> 1;
                    if ((nt & 1) == 0) { pa[mt][t][0] = e01; pa[mt][t][1] = e23; }
                    else               { pa[mt][t][2] = e01; pa[mt][t][3] = e23; }
                    a01 = __hadd2(a01, *reinterpret_cast<const __half2*>(&e01));
                    a23 = __hadd2(a23, *reinterpret_cast<const __half2*>(&e23));
                }
                const float2 f01 = __half22float2(a01);
                const float2 f23 = __half22float2(a23);
                rs[mt * 2 + 0] += f01.x + f01.y;
                rs[mt * 2 + 1] += f23.x + f23.y;
            }
        }
        const bool nochg = (al[0] == 1.0f) && (al[1] == 1.0f) &&
                           (al[2] == 1.0f) && (al[3] == 1.0f);
        if (!__all_sync(0xffffffffu, nochg)) {
#pragma unroll
            for (int mt = 0; mt < 2; mt++)
#pragma unroll
                for (int nt = 0; nt < 8; nt++) {
                    oacc[mt][nt][0] *= al[mt * 2];
                    oacc[mt][nt][1] *= al[mt * 2];
                    oacc[mt][nt][2] *= al[mt * 2 + 1];
                    oacc[mt][nt][3] *= al[mt * 2 + 1];
                }
        }
#pragma unroll
        for (int s = 0; s < 4; s++) {
            rs[s] += __shfl_xor_sync(0xffffffffu, rs[s], 1);
            rs[s] += __shfl_xor_sync(0xffffffffu, rs[s], 2);
            lr[s] = lr[s] * al[s] + rs[s];
            mr[s] = mn[s];
        }

        // ---- O += P V: 16 V-LDSM, 64 MMAs (frag reuse x2) ----
#pragma unroll
        for (int t = 0; t < 4; t++) {
#pragma unroll
            for (int db = 0; db < 4; db++) {
                unsigned r0, r1, r2, r3;
                ldsm_x4_t(r0, r1, r2, r3,
                          vb + (unsigned)((t * 16 * FST + db * 16) * 2));
                unsigned b0[2] = {r0, r1};
                unsigned b1[2] = {r2, r3};
#pragma unroll
                for (int mt = 0; mt < 2; mt++) {
                    mma16816h(oacc[mt][db * 2 + 0], pa[mt][t], b0);
                    mma16816h(oacc[mt][db * 2 + 1], pa[mt][t], b1);
                }
            }
        }

        __syncthreads();
        if (jt + 1 < NT) {
            if (jt + 2 < NT) {
                f_loadKV(kvbase, jt & 1, (jt + 2) * 64, Kf, Vf, tid);
                cpa_commit();
                cpa_wait<1>();
            } else {
                cpa_wait<0>();
            }
            __syncthreads();
        }
    }

    // ---- epilogue: write attention out as fp16 ----
    __half* Ch = g_Cf + hoff;
#pragma unroll
    for (int mt = 0; mt < 2; mt++) {
        const float inv0 = 1.0f / lr[mt * 2];
        const float inv1 = 1.0f / lr[mt * 2 + 1];
        const int row0 = q0 + wid * 32 + mt * 16 + (lane >> 2);
#pragma unroll
        for (int nt = 0; nt < 8; nt++) {
            const int d = nt * 8 + tg * 2;
            *(unsigned*)(Ch + (size_t)row0 * Dmodel + d) =
                packf16(oacc[mt][nt][0] * inv0, oacc[mt][nt][1] * inv0);
            *(unsigned*)(Ch + (size_t)(row0 + 8) * Dmodel + d) =
                packf16(oacc[mt][nt][2] * inv1, oacc[mt][nt][3] * inv1);
        }
    }
}

// ---------------------------------------------------------------------------
extern "C" void kernel_launch(void* const* d_in, const int* in_sizes, int n_in,
                              void* d_out, int out_size)
{
    const float* q  = (const float*)d_in[0];
    const float* k  = (const float*)d_in[1];
    const float* v  = (const float*)d_in[2];
    const float* Wq = (const float*)d_in[3];
    const float* bq = (const float*)d_in[4];
    const float* Wk = (const float*)d_in[5];
    const float* bk = (const float*)d_in[6];
    const float* Wv = (const float*)d_in[7];
    const float* bv = (const float*)d_in[8];
    const float* Wo = (const float*)d_in[9];
    const float* bo = (const float*)d_in[10];
    float* out = (float*)d_out;

    cudaFuncSetAttribute(flash_attn, cudaFuncAttributeMaxDynamicSharedMemorySize, FSMEM);
    cudaFuncSetAttribute(qkv_gemm, cudaFuncAttributeMaxDynamicSharedMemorySize, GSMEM);
    cudaFuncSetAttribute(out_gemm, cudaFuncAttributeMaxDynamicSharedMemorySize, GSMEM);

    conv_inputs<<<dim3(NELEM / 1024, 1, 3), 256>>>(q, k, v);
    conv_weights<<<dim3(WELEM / 1024, 1, 4), 256>>>(Wq, Wk, Wv, Wo);

    dim3 gqkv(Dmodel / 128, Mrows / 128, 3);   // 8 x 32 x 3
    qkv_gemm<<<gqkv, 256, GSMEM>>>(bq, bk, bv);

    dim3 gf(Nseq / 128, Bsz * Hh);             // 16 x 32
    flash_attn<<<gf, 128, FSMEM>>>();

    dim3 go(Dmodel / 128, Mrows / 128);        // 8 x 32
    out_gemm<<<go, 256, GSMEM>>>(bo, out);
}

// round 15
// speedup vs baseline: 1.2199x; 1.1657x over previous
#include <cuda_runtime.h>
#include <cuda_fp16.h>

// Problem constants
#define Bsz    2
#define Nseq   2048
#define Dmodel 1024
#define Hh     16
#define DKh    64
#define Mrows  4096
#define NELEM  (Mrows * Dmodel)     // 4,194,304
#define WELEM  (Dmodel * Dmodel)    // 1,048,576
#define SCALE  0.125f
#define QSCALE (0.125f * 1.44269504088896f)   // fold log2(e): softmax in exp2 domain

// ---- mma.sync / ldmatrix / cp.async helpers (base sm_80+ ISA) ----
__device__ __forceinline__ unsigned smem_u32(const void* p) {
    unsigned a;
    asm("{ .reg .u64 t; cvta.to.shared.u64 t, %1; cvt.u32.u64 %0, t; }" : "=r"(a) : "l"(p));
    return a;
}
__device__ __forceinline__ void ldsm_x4(unsigned& r0, unsigned& r1, unsigned& r2, unsigned& r3,
                                        unsigned addr) {
    asm volatile("ldmatrix.sync.aligned.m8n8.x4.shared.b16 {%0,%1,%2,%3}, [%4];"
                 : "=r"(r0), "=r"(r1), "=r"(r2), "=r"(r3) : "r"(addr));
}
__device__ __forceinline__ void ldsm_x4_t(unsigned& r0, unsigned& r1, unsigned& r2, unsigned& r3,
                                          unsigned addr) {
    asm volatile("ldmatrix.sync.aligned.m8n8.x4.trans.shared.b16 {%0,%1,%2,%3}, [%4];"
                 : "=r"(r0), "=r"(r1), "=r"(r2), "=r"(r3) : "r"(addr));
}
__device__ __forceinline__ void mma16816h(float* c, const unsigned* a, const unsigned* b) {
    asm volatile("mma.sync.aligned.m16n8k16.row.col.f32.f16.f16.f32 "
                 "{%0,%1,%2,%3},{%4,%5,%6,%7},{%8,%9},{%0,%1,%2,%3};"
                 : "+f"(c[0]), "+f"(c[1]), "+f"(c[2]), "+f"(c[3])
                 : "r"(a[0]), "r"(a[1]), "r"(a[2]), "r"(a[3]), "r"(b[0]), "r"(b[1]));
}
__device__ __forceinline__ void cpa16(unsigned dst, const void* src) {
    asm volatile("cp.async.cg.shared.global [%0], [%1], 16;" :: "r"(dst), "l"(src));
}
__device__ __forceinline__ void cpa_commit() { asm volatile("cp.async.commit_group;"); }
template<int N> __device__ __forceinline__ void cpa_wait() {
    asm volatile("cp.async.wait_group %0;" :: "n"(N));
}
__device__ __forceinline__ unsigned packf16(float x, float y) {
    __half2 t = __floats2half2_rn(x, y);
    return *reinterpret_cast<unsigned*>(&t);
}
__device__ __forceinline__ unsigned ex2h2(unsigned d) {
    unsigned e;
    asm("ex2.approx.f16x2 %0, %1;" : "=r"(e) : "r"(d));
    return e;
}

// ---- scratch (fp16) ----
__device__ __half g_xf[3 * NELEM];   // converted inputs q,k,v
__device__ __half g_wf[4 * WELEM];   // converted weights Wq,Wk,Wv,Wo
__device__ __half g_pf[3 * NELEM];   // projected Q(pre-scaled),K,V
__device__ __half g_Cf[NELEM];       // attention output

// ---------------------------------------------------------------------------
// Convert kernels: fp32 -> fp16  (round-11 proven)
// ---------------------------------------------------------------------------
__global__ __launch_bounds__(256) void conv_inputs(const float* __restrict__ q,
                                                   const float* __restrict__ k,
                                                   const float* __restrict__ v)
{
    const int z = blockIdx.z;
    const float* src = (z == 0) ? q : (z == 1) ? k : v;
    __half* dst = g_xf + (size_t)z * NELEM;
    const size_t i = ((size_t)blockIdx.x * 256 + threadIdx.x) * 4;
    float4 f = *(const float4*)(src + i);
    uint2 o;
    o.x = packf16(f.x, f.y);
    o.y = packf16(f.z, f.w);
    *(uint2*)(dst + i) = o;
}

__global__ __launch_bounds__(256) void conv_weights(const float* __restrict__ wq,
                                                    const float* __restrict__ wk,
                                                    const float* __restrict__ wv,
                                                    const float* __restrict__ wo)
{
    const int z = blockIdx.z;
    const float* src = (z == 0) ? wq : (z == 1) ? wk : (z == 2) ? wv : wo;
    __half* dst = g_wf + (size_t)z * WELEM;
    const size_t i = ((size_t)blockIdx.x * 256 + threadIdx.x) * 4;
    float4 f = *(const float4*)(src + i);
    uint2 o;
    o.x = packf16(f.x, f.y);
    o.y = packf16(f.z, f.w);
    *(uint2*)(dst + i) = o;
}

// ---------------------------------------------------------------------------
// fp16 HMMA GEMM, cp.async 2-stage: NOW 512 threads, 16 warps (4x4),
// warp tile 32x32 -> 32 regs of accumulator -> 2 CTAs/SM (32 warps) target.
// CTA tile 128x128, Kc=64.
// ---------------------------------------------------------------------------
#define KC 64
#define NCH (Dmodel / KC)     // 16
#define GST 72
#define GBUF (128 * GST * 2)  // 18432 B
#define GSTAGE (2 * GBUF)     // 36864 B
#define GSMEM (2 * GSTAGE)    // 73728 B

__device__ __forceinline__ void g_load(unsigned sbase, int stage,
                                       const __half* Xf, const __half* Wf,
                                       int m0, int n0, int k0, int tid)
{
    // 512 threads: each loads 32B of A and 32B of B
    const int row = tid >> 2;              // 0..127
    const int q   = tid & 3;               // quarter of 64-col chunk
    const unsigned dst0 = sbase + (unsigned)(stage * GSTAGE + row * 144 + q * 32);
    const size_t asrc = (size_t)(m0 + row) * Dmodel + k0 + q * 16;
    const size_t bsrc = (size_t)(n0 + row) * Dmodel + k0 + q * 16;
    cpa16(dst0,             Xf + asrc);
    cpa16(dst0 + 16,        Xf + asrc + 8);
    cpa16(dst0 + GBUF,      Wf + bsrc);
    cpa16(dst0 + GBUF + 16, Wf + bsrc + 8);
}

__device__ __forceinline__ void gemm_body(const __half* __restrict__ Xf,
                                          const __half* __restrict__ Wf,
                                          const float* __restrict__ bias,
                                          __half* C16, float* Cf, float cscale)
{
    extern __shared__ __align__(16) char smg[];
    const unsigned sbase = smem_u32(smg);

    const int tid  = threadIdx.x;          // 0..511
    const int wid  = tid >> 5;             // 0..15
    const int lane = tid & 31;
    const int wm   = wid >> 2;             // 0..3 (32-row slab)
    const int wn   = wid & 3;              // 0..3 (32-col slab)
    const int m0   = blockIdx.y * 128;
    const int n0   = blockIdx.x * 128;

    float acc[2][4][4];
#pragma unroll
    for (int mt = 0; mt < 2; mt++)
#pragma unroll
        for (int nt = 0; nt < 4; nt++)
#pragma unroll
            for (int i = 0; i < 4; i++) acc[mt][nt][i] = 0.0f;

    const unsigned a_off = (unsigned)(((wm * 32 + (lane & 15)) * GST + (lane >> 4) * 8) * 2);
    const unsigned b_off = (unsigned)(((wn * 32 + (lane & 15)) * GST + (lane >> 4) * 8) * 2);

    g_load(sbase, 0, Xf, Wf, m0, n0, 0, tid);
    cpa_commit();
    g_load(sbase, 1, Xf, Wf, m0, n0, KC, tid);
    cpa_commit();
    cpa_wait<1>();
    __syncthreads();

    for (int ch = 0; ch < NCH; ch++) {
        const unsigned st = sbase + (unsigned)((ch & 1) * GSTAGE);
        const unsigned abase = st + a_off;
        const unsigned bbase = st + GBUF + b_off;

#pragma unroll
        for (int ks = 0; ks < 4; ks++) {
            const unsigned koff = (unsigned)(ks * 16 * 2);
            unsigned bf[4][2];
#pragma unroll
            for (int np = 0; np < 2; np++) {
                unsigned r0, r1, r2, r3;
                ldsm_x4(r0, r1, r2, r3,
                        bbase + koff + (unsigned)(np * 16 * GST * 2));
                bf[np * 2 + 0][0] = r0; bf[np * 2 + 0][1] = r2;
                bf[np * 2 + 1][0] = r1; bf[np * 2 + 1][1] = r3;
            }
            unsigned af[2][4];
#pragma unroll
            for (int mt = 0; mt < 2; mt++)
                ldsm_x4(af[mt][0], af[mt][1], af[mt][2], af[mt][3],
                        abase + koff + (unsigned)(mt * 16 * GST * 2));
#pragma unroll
            for (int mt = 0; mt < 2; mt++)
#pragma unroll
                for (int nt = 0; nt < 4; nt++)
                    mma16816h(acc[mt][nt], af[mt], bf[nt]);
        }
        __syncthreads();

        if (ch + 1 < NCH) {
            if (ch + 2 < NCH) {
                g_load(sbase, ch & 1, Xf, Wf, m0, n0, (ch + 2) * KC, tid);
                cpa_commit();
                cpa_wait<1>();
            } else {
                cpa_wait<0>();
            }
            __syncthreads();
        }
    }

    const int g   = lane >> 2;
    const int tig = lane & 3;
#pragma unroll
    for (int mt = 0; mt < 2; mt++) {
        const int r0 = m0 + wm * 32 + mt * 16 + g;
#pragma unroll
        for (int nt = 0; nt < 4; nt++) {
            const int cidx = n0 + wn * 32 + nt * 8 + tig * 2;
            const float2 bv = *(const float2*)(bias + cidx);
            const float x0 = acc[mt][nt][0] + bv.x;
            const float x1 = acc[mt][nt][1] + bv.y;
            const float x2 = acc[mt][nt][2] + bv.x;
            const float x3 = acc[mt][nt][3] + bv.y;
            if (Cf) {
                *(float2*)(Cf + (size_t)r0 * Dmodel + cidx) = make_float2(x0, x1);
                *(float2*)(Cf + (size_t)(r0 + 8) * Dmodel + cidx) = make_float2(x2, x3);
            } else {
                *(unsigned*)(C16 + (size_t)r0 * Dmodel + cidx) =
                    packf16(x0 * cscale, x1 * cscale);
                *(unsigned*)(C16 + (size_t)(r0 + 8) * Dmodel + cidx) =
                    packf16(x2 * cscale, x3 * cscale);
            }
        }
    }
}

__global__ __launch_bounds__(512, 2) void qkv_gemm(const float* __restrict__ bq,
                                                   const float* __restrict__ bk,
                                                   const float* __restrict__ bv)
{
    const int z = blockIdx.z;
    const float* bias = (z == 0) ? bq : (z == 1) ? bk : bv;
    const float cs = (z == 0) ? QSCALE : 1.0f;
    gemm_body(g_xf + (size_t)z * NELEM, g_wf + (size_t)z * WELEM,
              bias, g_pf + (size_t)z * NELEM, nullptr, cs);
}

__global__ __launch_bounds__(512, 2) void out_gemm(const float* __restrict__ bo,
                                                   float* __restrict__ out)
{
    gemm_body(g_Cf, g_wf + (size_t)3 * WELEM, bo, nullptr, out, 1.0f);
}

// ---------------------------------------------------------------------------
// Flash attention — EXACT round-11 configuration (best measured: 135.4 us).
// fp16 HMMA, cp.async 2-stage K/V pipeline, 8 warps x 16 q-rows, 256 thr.
// half2 softmax via ex2.approx.f16x2; software-pipelined ldsm rings.
// ---------------------------------------------------------------------------
#define FST 72
#define QBUF  (128 * FST * 2)     // 18432
#define KVBUF (64 * FST * 2)      // 9216
#define KVSTAGE (2 * KVBUF)       // 18432
#define FSMEM (QBUF + 2 * KVSTAGE)   // 55296

__device__ __forceinline__ void f_loadKV(unsigned kvbase, int stage, int jt,
                                         const __half* Kf, const __half* Vf, int tid)
{
    const int row = tid >> 2;
    const int c2  = tid & 3;
    const unsigned dst0 = kvbase + (unsigned)(stage * KVSTAGE + row * 144 + c2 * 32);
    const size_t src = (size_t)(jt + row) * Dmodel + c2 * 16;
    cpa16(dst0,              Kf + src);
    cpa16(dst0 + 16,         Kf + src + 8);
    cpa16(dst0 + KVBUF,      Vf + src);
    cpa16(dst0 + KVBUF + 16, Vf + src + 8);
}

__global__ __launch_bounds__(256, 2) void flash_attn()
{
    extern __shared__ __align__(16) char smf[];
    const unsigned sbase  = smem_u32(smf);
    const unsigned kvbase = sbase + QBUF;

    const int tid  = threadIdx.x;
    const int wid  = tid >> 5;
    const int lane = tid & 31;
    const int tg   = lane & 3;
    const int bh   = blockIdx.y;
    const int b    = bh >> 4;
    const int h    = bh & 15;
    const int q0   = blockIdx.x * 128;

    const size_t hoff = (size_t)b * Nseq * Dmodel + h * DKh;
    const __half* Qf = g_pf + hoff;
    const __half* Kf = g_pf + NELEM + hoff;
    const __half* Vf = g_pf + 2 * NELEM + hoff;

    // prologue
    {
        const int row = tid >> 1;
        const int c4  = tid & 1;
        const unsigned dq = sbase + (unsigned)(row * 144 + c4 * 64);
        const size_t src = (size_t)(q0 + row) * Dmodel + c4 * 32;
#pragma unroll
        for (int j = 0; j < 4; j++)
            cpa16(dq + j * 16, Qf + src + j * 8);
    }
    f_loadKV(kvbase, 0, 0, Kf, Vf, tid);
    cpa_commit();
    f_loadKV(kvbase, 1, 64, Kf, Vf, tid);
    cpa_commit();
    cpa_wait<1>();
    __syncthreads();

    // persistent Q fragments
    const unsigned qa = sbase +
        (unsigned)(((wid * 16 + (lane & 15)) * FST + (lane >> 4) * 8) * 2);
    unsigned aq[4][4];
#pragma unroll
    for (int ks = 0; ks < 4; ks++)
        ldsm_x4(aq[ks][0], aq[ks][1], aq[ks][2], aq[ks][3], qa + ks * 32);

    const unsigned kb_off = (unsigned)(((lane & 15) * FST + (lane >> 4) * 8) * 2);

    float oacc[8][4];
#pragma unroll
    for (int nt = 0; nt < 8; nt++)
#pragma unroll
        for (int i = 0; i < 4; i++) oacc[nt][i] = 0.0f;
    float mr0 = -1e30f, mr1 = -1e30f, lr0 = 0.0f, lr1 = 0.0f;

    const int NT = Nseq / 64;   // 32
    for (int jt = 0; jt < NT; jt++) {
        const unsigned st = kvbase + (unsigned)((jt & 1) * KVSTAGE);
        const unsigned kb = st + kb_off;
        const unsigned vb = st + KVBUF + kb_off;

        // ---- S = Q K^T (log2 domain; scale pre-folded into Q) ----
        float sacc[8][4];
#pragma unroll
        for (int nt = 0; nt < 8; nt++)
#pragma unroll
            for (int i = 0; i < 4; i++) sacc[nt][i] = 0.0f;

        {
            unsigned kf[2][4];
            ldsm_x4(kf[0][0], kf[0][1], kf[0][2], kf[0][3], kb);
#pragma unroll
            for (int it = 0; it < 16; it++) {
                const int ks = it >> 2, jb = it & 3;
                if (it + 1 < 16) {
                    const int ks2 = (it + 1) >> 2, jb2 = (it + 1) & 3;
                    ldsm_x4(kf[(it + 1) & 1][0], kf[(it + 1) & 1][1],
                            kf[(it + 1) & 1][2], kf[(it + 1) & 1][3],
                            kb + (unsigned)((jb2 * 16 * FST + ks2 * 16) * 2));
                }
                unsigned bf0[2] = {kf[it & 1][0], kf[it & 1][2]};
                unsigned bf1[2] = {kf[it & 1][1], kf[it & 1][3]};
                mma16816h(sacc[jb * 2 + 0], aq[ks], bf0);
                mma16816h(sacc[jb * 2 + 1], aq[ks], bf1);
            }
        }

        // ---- online softmax (half2 exp; ex2 output IS the PV fragment) ----
        float mx0 = -1e30f, mx1 = -1e30f;
#pragma unroll
        for (int nt = 0; nt < 8; nt++) {
            mx0 = fmaxf(mx0, fmaxf(sacc[nt][0], sacc[nt][1]));
            mx1 = fmaxf(mx1, fmaxf(sacc[nt][2], sacc[nt][3]));
        }
        mx0 = fmaxf(mx0, __shfl_xor_sync(0xffffffffu, mx0, 1));
        mx0 = fmaxf(mx0, __shfl_xor_sync(0xffffffffu, mx0, 2));
        mx1 = fmaxf(mx1, __shfl_xor_sync(0xffffffffu, mx1, 1));
        mx1 = fmaxf(mx1, __shfl_xor_sync(0xffffffffu, mx1, 2));
        const float mn0 = fmaxf(mr0, mx0);
        const float mn1 = fmaxf(mr1, mx1);
        const float al0 = exp2f(mr0 - mn0);
        const float al1 = exp2f(mr1 - mn1);

        unsigned pa[4][4];
        float rs0 = 0.0f, rs1 = 0.0f;
#pragma unroll
        for (int grp = 0; grp < 2; grp++) {
            __half2 a01 = __float2half2_rn(0.0f);
            __half2 a23 = __float2half2_rn(0.0f);
#pragma unroll
            for (int k2 = 0; k2 < 4; k2++) {
                const int nt = grp * 4 + k2;
                const unsigned e01 = ex2h2(packf16(sacc[nt][0] - mn0, sacc[nt][1] - mn0));
                const unsigned e23 = ex2h2(packf16(sacc[nt][2] - mn1, sacc[nt][3] - mn1));
                const int t = nt >> 1;
                if ((nt & 1) == 0) { pa[t][0] = e01; pa[t][1] = e23; }
                else               { pa[t][2] = e01; pa[t][3] = e23; }
                a01 = __hadd2(a01, *reinterpret_cast<const __half2*>(&e01));
                a23 = __hadd2(a23, *reinterpret_cast<const __half2*>(&e23));
            }
            const float2 f01 = __half22float2(a01);
            const float2 f23 = __half22float2(a23);
            rs0 += f01.x + f01.y;
            rs1 += f23.x + f23.y;
        }
        const bool nochg = (al0 == 1.0f) && (al1 == 1.0f);
        if (!__all_sync(0xffffffffu, nochg)) {
#pragma unroll
            for (int nt = 0; nt < 8; nt++) {
                oacc[nt][0] *= al0; oacc[nt][1] *= al0;
                oacc[nt][2] *= al1; oacc[nt][3] *= al1;
            }
        }
        rs0 += __shfl_xor_sync(0xffffffffu, rs0, 1);
        rs0 += __shfl_xor_sync(0xffffffffu, rs0, 2);
        rs1 += __shfl_xor_sync(0xffffffffu, rs1, 1);
        rs1 += __shfl_xor_sync(0xffffffffu, rs1, 2);
        lr0 = lr0 * al0 + rs0;
        lr1 = lr1 * al1 + rs1;
        mr0 = mn0; mr1 = mn1;

        // ---- O += P V (software-pipelined V-frag loads) ----
        {
            unsigned vf[2][4];
            ldsm_x4_t(vf[0][0], vf[0][1], vf[0][2], vf[0][3], vb);
#pragma unroll
            for (int it = 0; it < 16; it++) {
                const int t = it >> 2, db = it & 3;
                if (it + 1 < 16) {
                    const int t2 = (it + 1) >> 2, db2 = (it + 1) & 3;
                    ldsm_x4_t(vf[(it + 1) & 1][0], vf[(it + 1) & 1][1],
                              vf[(it + 1) & 1][2], vf[(it + 1) & 1][3],
                              vb + (unsigned)((t2 * 16 * FST + db2 * 16) * 2));
                }
                unsigned b0[2] = {vf[it & 1][0], vf[it & 1][1]};
                unsigned b1[2] = {vf[it & 1][2], vf[it & 1][3]};
                mma16816h(oacc[db * 2 + 0], pa[t], b0);
                mma16816h(oacc[db * 2 + 1], pa[t], b1);
            }
        }

        __syncthreads();
        if (jt + 1 < NT) {
            if (jt + 2 < NT) {
                f_loadKV(kvbase, jt & 1, (jt + 2) * 64, Kf, Vf, tid);
                cpa_commit();
                cpa_wait<1>();
            } else {
                cpa_wait<0>();
            }
            __syncthreads();
        }
    }

    // ---- epilogue: write attention out as fp16 ----
    const float inv0 = 1.0f / lr0;
    const float inv1 = 1.0f / lr1;
    __half* Ch = g_Cf + hoff;
    const int row0 = q0 + wid * 16 + (lane >> 2);
#pragma unroll
    for (int nt = 0; nt < 8; nt++) {
        const int d = nt * 8 + tg * 2;
        *(unsigned*)(Ch + (size_t)row0 * Dmodel + d) =
            packf16(oacc[nt][0] * inv0, oacc[nt][1] * inv0);
        *(unsigned*)(Ch + (size_t)(row0 + 8) * Dmodel + d) =
            packf16(oacc[nt][2] * inv1, oacc[nt][3] * inv1);
    }
}

// ---------------------------------------------------------------------------
extern "C" void kernel_launch(void* const* d_in, const int* in_sizes, int n_in,
                              void* d_out, int out_size)
{
    const float* q  = (const float*)d_in[0];
    const float* k  = (const float*)d_in[1];
    const float* v  = (const float*)d_in[2];
    const float* Wq = (const float*)d_in[3];
    const float* bq = (const float*)d_in[4];
    const float* Wk = (const float*)d_in[5];
    const float* bk = (const float*)d_in[6];
    const float* Wv = (const float*)d_in[7];
    const float* bv = (const float*)d_in[8];
    const float* Wo = (const float*)d_in[9];
    const float* bo = (const float*)d_in[10];
    float* out = (float*)d_out;

    cudaFuncSetAttribute(flash_attn, cudaFuncAttributeMaxDynamicSharedMemorySize, FSMEM);
    cudaFuncSetAttribute(qkv_gemm, cudaFuncAttributeMaxDynamicSharedMemorySize, GSMEM);
    cudaFuncSetAttribute(out_gemm, cudaFuncAttributeMaxDynamicSharedMemorySize, GSMEM);

    conv_inputs<<<dim3(NELEM / 1024, 1, 3), 256>>>(q, k, v);
    conv_weights<<<dim3(WELEM / 1024, 1, 4), 256>>>(Wq, Wk, Wv, Wo);

    dim3 gqkv(Dmodel / 128, Mrows / 128, 3);   // 8 x 32 x 3
    qkv_gemm<<<gqkv, 512, GSMEM>>>(bq, bk, bv);

    dim3 gf(Nseq / 128, Bsz * Hh);             // 16 x 32
    flash_attn<<<gf, 256, FSMEM>>>();

    dim3 go(Dmodel / 128, Mrows / 128);        // 8 x 32
    out_gemm<<<go, 512, GSMEM>>>(bo, out);
}